// round 8
// baseline (speedup 1.0000x reference)
#include <cuda_runtime.h>

// Problem constants
#define TT 16384
#define HH 100
#define GG 400   // 4*H

// Scratch (device globals)
__device__ float g_xg[TT * GG];   // input gate contributions [T, 4H]
__device__ float g_hs[TT * HH];   // hidden states [t][u]

// ---------------------------------------------------------------------------
__device__ __forceinline__ float2 ffma2(float2 a, float2 b, float2 c) {
    float2 r;
    asm("fma.rn.f32x2 %0, %1, %2, %3;"
        : "=l"(reinterpret_cast<unsigned long long&>(r))
        : "l"(reinterpret_cast<unsigned long long&>(a)),
          "l"(reinterpret_cast<unsigned long long&>(b)),
          "l"(reinterpret_cast<unsigned long long&>(c)));
    return r;
}
__device__ __forceinline__ float2 fadd2(float2 a, float2 b) {
    float2 r;
    asm("add.rn.f32x2 %0, %1, %2;"
        : "=l"(reinterpret_cast<unsigned long long&>(r))
        : "l"(reinterpret_cast<unsigned long long&>(a)),
          "l"(reinterpret_cast<unsigned long long&>(b)));
    return r;
}
__device__ __forceinline__ float ex2_approx(float x) {
    float r; asm("ex2.approx.f32 %0, %1;" : "=f"(r) : "f"(x)); return r;
}
__device__ __forceinline__ float rcp_approx(float x) {
    float r; asm("rcp.approx.f32 %0, %1;" : "=f"(r) : "f"(x)); return r;
}

#define LOG2E 1.4426950408889634f

__device__ __forceinline__ float tanh_fast(float x) {
    float e = ex2_approx(-2.0f * LOG2E * x);
    return fmaf(2.0f, rcp_approx(1.0f + e), -1.0f);
}

// ---------------------------------------------------------------------------
// Kernel 1: x_gates[t][j] = b_ih[j] + b_hh[j] + sum_k x[t][k]*W_ih[j][k]
// ---------------------------------------------------------------------------
__global__ void k_xgates(const float* __restrict__ x,
                         const float* __restrict__ Wih,
                         const float* __restrict__ bih,
                         const float* __restrict__ bhh) {
    int idx = blockIdx.x * blockDim.x + threadIdx.x;
    if (idx >= TT * GG) return;
    int t = idx / GG;
    int j = idx - t * GG;
    const float* xr = x + t * 3;
    const float* wr = Wih + j * 3;
    float s = bih[j] + bhh[j];
    s += xr[0] * wr[0] + xr[1] * wr[1] + xr[2] * wr[2];
    g_xg[idx] = s;
}

// ---------------------------------------------------------------------------
// Fused LSTM + projection. ONE block, 200 threads (6.25 warps).
// Thread pair (2u, 2u+1) = unit u; even: rows (i,f), odd: rows (g,o).
// 200 weight floats in registers per thread; dot product in EIGHT
// independent 12/13-deep FFMA2 chains (halved critical path vs R7).
// Input contributions prefetched from precomputed g_xg (L2-resident;
// depth-2 LDG pipeline) -- this frees the registers the extra chains use.
// One shfl_xor pair-exchange, replicated c/h tail, one barrier per step.
// ---------------------------------------------------------------------------
__global__ void __launch_bounds__(200, 1)
k_lstm_fused(const float* __restrict__ Whh,
             const float* __restrict__ Wlin,
             const float* __restrict__ blin,
             float* __restrict__ out) {
    __shared__ __align__(16) float sh[2][HH];          // h double buffer
    __shared__ float sWl[HH];
    __shared__ float sbl;

    const int tid = threadIdx.x;          // 0..199
    const int odd = tid & 1;
    const int u   = tid >> 1;             // 0..99
    const unsigned mask = (tid >= 192) ? 0x000000FFu : 0xFFFFFFFFu;

    const int r0 = odd * 2 * HH + u;      // even: i-row, odd: g-row
    const int r1 = r0 + HH;               // even: f-row, odd: o-row

    // slot0: even->sigmoid, odd->tanh ; slot1: sigmoid
    const float K0 = odd ? (-2.0f * LOG2E) : (-LOG2E);
    const float A0 = odd ? 2.0f : 1.0f;
    const float B0 = odd ? -1.0f : 0.0f;

    // Both weight rows -> registers (2 x 50 float2 = 200 regs)
    float2 w0[50], w1[50];
    {
        const float2* p0 = reinterpret_cast<const float2*>(Whh + r0 * HH);
        const float2* p1 = reinterpret_cast<const float2*>(Whh + r1 * HH);
        #pragma unroll
        for (int i = 0; i < 50; i++) { w0[i] = p0[i]; w1[i] = p1[i]; }
    }

    if (tid < HH) sWl[tid] = Wlin[tid];
    if (tid == 0) sbl = blin[0];
    if (tid < 2 * HH) (&sh[0][0])[tid] = 0.0f;
    __syncthreads();

    float c = 0.0f;

    // depth-2 x_gates prefetch (L2-resident stream)
    const float* xgp = g_xg;
    float ca0 = xgp[r0],      ca1 = xgp[r1];
    float na0 = xgp[GG + r0], na1 = xgp[GG + r1];

    const float4* hp0 = reinterpret_cast<const float4*>(&sh[0][0]);
    const float4* hp1 = reinterpret_cast<const float4*>(&sh[1][0]);

#define BODY(T, RP, WROW)                                                     \
    {                                                                         \
        const float xg0 = ca0, xg1 = ca1;                                     \
        ca0 = na0; ca1 = na1;                                                 \
        {                                                                     \
            int tp = (T) + 2; if (tp > TT - 1) tp = TT - 1;                   \
            const float* pp = g_xg + tp * GG;                                 \
            na0 = __ldg(pp + r0); na1 = __ldg(pp + r1);                       \
        }                                                                     \
        /* 8 independent chains, depth 12/13 */                               \
        float2 c00 = make_float2(xg0, 0.f), c01 = make_float2(0.f, 0.f);      \
        float2 c10 = make_float2(xg1, 0.f), c11 = make_float2(0.f, 0.f);      \
        float2 d00 = make_float2(0.f, 0.f), d01 = make_float2(0.f, 0.f);      \
        float2 d10 = make_float2(0.f, 0.f), d11 = make_float2(0.f, 0.f);      \
        _Pragma("unroll")                                                     \
        for (int i = 0; i < 13; i++) {                                        \
            float4 hv = (RP)[i];                                              \
            float2 lo = make_float2(hv.x, hv.y);                              \
            float2 hi = make_float2(hv.z, hv.w);                              \
            c00 = ffma2(lo, w0[2*i],   c00);  c01 = ffma2(hi, w0[2*i+1], c01);\
            c10 = ffma2(lo, w1[2*i],   c10);  c11 = ffma2(hi, w1[2*i+1], c11);\
        }                                                                     \
        _Pragma("unroll")                                                     \
        for (int i = 13; i < 25; i++) {                                       \
            float4 hv = (RP)[i];                                              \
            float2 lo = make_float2(hv.x, hv.y);                              \
            float2 hi = make_float2(hv.z, hv.w);                              \
            d00 = ffma2(lo, w0[2*i],   d00);  d01 = ffma2(hi, w0[2*i+1], d01);\
            d10 = ffma2(lo, w1[2*i],   d10);  d11 = ffma2(hi, w1[2*i+1], d11);\
        }                                                                     \
        float2 s0 = fadd2(fadd2(c00, d00), fadd2(c01, d01));                  \
        float2 s1 = fadd2(fadd2(c10, d10), fadd2(c11, d11));                  \
        float gt0 = s0.x + s0.y;                                              \
        float gt1 = s1.x + s1.y;                                              \
        /* activations (branch-free, per-slot constants) */                   \
        float e0 = ex2_approx(K0 * gt0);                                      \
        float a0 = fmaf(A0, rcp_approx(1.0f + e0), B0);                       \
        float e1 = ex2_approx(-LOG2E * gt1);                                  \
        float a1 = rcp_approx(1.0f + e1);                                     \
        /* pair exchange */                                                   \
        float p0 = __shfl_xor_sync(mask, a0, 1);                              \
        float p1 = __shfl_xor_sync(mask, a1, 1);                              \
        float ai = odd ? p0 : a0;                                             \
        float af = odd ? p1 : a1;                                             \
        float ag = odd ? a0 : p0;                                             \
        float ao = odd ? a1 : p1;                                             \
        c = fmaf(af, c, ai * ag);                                             \
        float hn = ao * tanh_fast(c);                                         \
        if (!odd) {                                                           \
            (WROW)[u] = hn;                                                   \
            g_hs[(T) * HH + u] = hn;                                          \
        }                                                                     \
        __syncthreads();                                                      \
    }

    #pragma unroll 1
    for (int t = 0; t < TT; t += 2) {
        BODY(t,     hp0, &sh[1][0])
        BODY(t + 1, hp1, &sh[0][0])
    }
#undef BODY

    // ---- projection tail: out[t] = sigmoid(sum_u hs[t][u]*Wl[u] + b) ----
    const float bl = sbl;
    for (int t = tid; t < TT; t += 200) {
        const float4* hr = reinterpret_cast<const float4*>(g_hs + t * HH);
        float s0 = 0.0f, s1 = 0.0f;
        #pragma unroll
        for (int j = 0; j < 25; j++) {
            float4 hv = hr[j];
            const float* wl = sWl + 4 * j;
            s0 = fmaf(hv.x, wl[0], s0);
            s1 = fmaf(hv.y, wl[1], s1);
            s0 = fmaf(hv.z, wl[2], s0);
            s1 = fmaf(hv.w, wl[3], s1);
        }
        float z = s0 + s1 + bl;
        out[t] = rcp_approx(1.0f + ex2_approx(-LOG2E * z));
    }
}

// ---------------------------------------------------------------------------
// Launch.  Inputs: input_x, W_ih, W_hh, b_ih, b_hh, W_lin, b_lin
// ---------------------------------------------------------------------------
extern "C" void kernel_launch(void* const* d_in, const int* in_sizes, int n_in,
                              void* d_out, int out_size) {
    const float* x    = (const float*)d_in[0];
    const float* Wih  = (const float*)d_in[1];
    const float* Whh  = (const float*)d_in[2];
    const float* bih  = (const float*)d_in[3];
    const float* bhh  = (const float*)d_in[4];
    const float* Wlin = (const float*)d_in[5];
    const float* blin = (const float*)d_in[6];
    float* out = (float*)d_out;

    (void)in_sizes; (void)n_in; (void)out_size;

    {
        int n = TT * GG;
        k_xgates<<<(n + 255) / 256, 256>>>(x, Wih, bih, bhh);
    }
    k_lstm_fused<<<1, 200>>>(Whh, Wlin, blin, out);
}

// round 9
// speedup vs baseline: 1.1723x; 1.1723x over previous
#include <cuda_runtime.h>

// Problem constants
#define TT 16384
#define HH 100

// Hidden states [t][u]
__device__ float g_hs[TT * HH];

// ---------------------------------------------------------------------------
__device__ __forceinline__ float2 ffma2(float2 a, float2 b, float2 c) {
    float2 r;
    asm("fma.rn.f32x2 %0, %1, %2, %3;"
        : "=l"(reinterpret_cast<unsigned long long&>(r))
        : "l"(reinterpret_cast<unsigned long long&>(a)),
          "l"(reinterpret_cast<unsigned long long&>(b)),
          "l"(reinterpret_cast<unsigned long long&>(c)));
    return r;
}
__device__ __forceinline__ float2 fadd2(float2 a, float2 b) {
    float2 r;
    asm("add.rn.f32x2 %0, %1, %2;"
        : "=l"(reinterpret_cast<unsigned long long&>(r))
        : "l"(reinterpret_cast<unsigned long long&>(a)),
          "l"(reinterpret_cast<unsigned long long&>(b)));
    return r;
}
// Single-instruction tanh (MUFU.TANH, sm_75+)
__device__ __forceinline__ float tanh_approx(float x) {
    float r; asm("tanh.approx.f32 %0, %1;" : "=f"(r) : "f"(x)); return r;
}
__device__ __forceinline__ float ex2_approx(float x) {
    float r; asm("ex2.approx.f32 %0, %1;" : "=f"(r) : "f"(x)); return r;
}
__device__ __forceinline__ float rcp_approx(float x) {
    float r; asm("rcp.approx.f32 %0, %1;" : "=f"(r) : "f"(x)); return r;
}

#define LOG2E 1.4426950408889634f

// sigmoid(x) = 0.5*tanh(0.5x) + 0.5  (FMUL + MUFU.TANH + FFMA)
__device__ __forceinline__ float sigmoid_t(float x) {
    return fmaf(0.5f, tanh_approx(0.5f * x), 0.5f);
}

// ---------------------------------------------------------------------------
// Fused LSTM + projection. ONE block, 200 threads (6.25 warps).
// Thread pair (2u, 2u+1) handles unit u:
//   even thread: gate rows i (u), f (100+u)          -> both sigmoid
//   odd  thread: gate rows g (200+u), o (300+u)      -> tanh, sigmoid
// 200 weight floats in registers (255-reg cap at 200 threads -> no spill).
// Per step: 25 broadcast LDS.128 + 100 FFMA2 (4 indep 25-deep chains),
// activations via single MUFU.TANH (sigmoid = scaled tanh), ONE shfl_xor
// pair-exchange, replicated c/h tail, one barrier.
// ---------------------------------------------------------------------------
__global__ void __launch_bounds__(200, 1)
k_lstm_fused(const float* __restrict__ x,
             const float* __restrict__ Whh,
             const float* __restrict__ Wih,
             const float* __restrict__ bih,
             const float* __restrict__ bhh,
             const float* __restrict__ Wlin,
             const float* __restrict__ blin,
             float* __restrict__ out) {
    extern __shared__ __align__(16) float sx[];        // [TT*3] input (192 KB)
    __shared__ __align__(16) float sh[2][HH];          // h double buffer
    __shared__ float sWl[HH];
    __shared__ float sbl;

    const int tid = threadIdx.x;          // 0..199
    const int odd = tid & 1;
    const int u   = tid >> 1;             // 0..99
    // Warp 6 holds only threads 192..199 (lanes 0..7)
    const unsigned mask = (tid >= 192) ? 0x000000FFu : 0xFFFFFFFFu;

    const int r0 = odd * 2 * HH + u;      // even: i-row, odd: g-row
    const int r1 = r0 + HH;               // even: f-row, odd: o-row

    // slot0 activation a = A0*tanh(S0*g) + B0:
    //   even (sigmoid): S0=0.5, A0=0.5, B0=0.5
    //   odd  (tanh):    S0=1.0, A0=1.0, B0=0.0
    const float S0 = odd ? 1.0f : 0.5f;
    const float A0 = odd ? 1.0f : 0.5f;
    const float B0 = odd ? 0.0f : 0.5f;

    // Both weight rows -> registers (2 x 50 float2 = 200 regs)
    float2 w0[50], w1[50];
    {
        const float2* p0 = reinterpret_cast<const float2*>(Whh + r0 * HH);
        const float2* p1 = reinterpret_cast<const float2*>(Whh + r1 * HH);
        #pragma unroll
        for (int i = 0; i < 50; i++) { w0[i] = p0[i]; w1[i] = p1[i]; }
    }
    const float wa0 = Wih[r0 * 3], wa1 = Wih[r0 * 3 + 1], wa2 = Wih[r0 * 3 + 2];
    const float wb0 = Wih[r1 * 3], wb1 = Wih[r1 * 3 + 1], wb2 = Wih[r1 * 3 + 2];
    const float bias0 = bih[r0] + bhh[r0];
    const float bias1 = bih[r1] + bhh[r1];

    // Preload x into SMEM (coalesced float4); stage W_lin; zero h buffers
    {
        const float4* xs = reinterpret_cast<const float4*>(x);
        float4* xd = reinterpret_cast<float4*>(sx);
        for (int i = tid; i < TT * 3 / 4; i += 200) xd[i] = xs[i];
    }
    if (tid < HH) sWl[tid] = Wlin[tid];
    if (tid == 0) sbl = blin[0];
    if (tid < 2 * HH) (&sh[0][0])[tid] = 0.0f;
    __syncthreads();

    float c = 0.0f;
    const float* xr = sx;

    #pragma unroll 1
    for (int t = 0; t < TT; t++, xr += 3) {
        // Input contributions for both rows (3 broadcast LDS.32, 6 FFMA)
        const float xv0 = xr[0], xv1 = xr[1], xv2 = xr[2];
        float xg0 = fmaf(wa2, xv2, fmaf(wa1, xv1, fmaf(wa0, xv0, bias0)));
        float xg1 = fmaf(wb2, xv2, fmaf(wb1, xv1, fmaf(wb0, xv0, bias1)));

        // Dual 100-wide dot products: 25 LDS.128 + 100 FFMA2 (4 indep chains)
        const float4* hp = reinterpret_cast<const float4*>(&sh[t & 1][0]);
        float2 a00 = make_float2(xg0, 0.0f), a01 = make_float2(0.0f, 0.0f);
        float2 a10 = make_float2(xg1, 0.0f), a11 = make_float2(0.0f, 0.0f);
        #pragma unroll
        for (int i = 0; i < 25; i++) {
            float4 hv = hp[i];
            float2 lo = make_float2(hv.x, hv.y);
            float2 hi = make_float2(hv.z, hv.w);
            a00 = ffma2(lo, w0[2 * i],     a00);
            a01 = ffma2(hi, w0[2 * i + 1], a01);
            a10 = ffma2(lo, w1[2 * i],     a10);
            a11 = ffma2(hi, w1[2 * i + 1], a11);
        }
        float2 s0 = fadd2(a00, a01);
        float2 s1 = fadd2(a10, a11);
        float gt0 = s0.x + s0.y;
        float gt1 = s1.x + s1.y;

        // Activations: 1 MUFU.TANH each (sigmoid = scaled tanh)
        float a0 = fmaf(A0, tanh_approx(S0 * gt0), B0);
        float a1 = sigmoid_t(gt1);

        // Pair exchange: partner differs in lane bit 0
        float p0 = __shfl_xor_sync(mask, a0, 1);
        float p1 = __shfl_xor_sync(mask, a1, 1);
        // even: i=a0 f=a1 g=p0 o=p1 ; odd: i=p0 f=p1 g=a0 o=a1
        float ai = odd ? p0 : a0;
        float af = odd ? p1 : a1;
        float ag = odd ? a0 : p0;
        float ao = odd ? a1 : p1;

        // Replicated c/h update (identical on both pair threads)
        c = fmaf(af, c, ai * ag);
        float hn = ao * tanh_approx(c);

        if (!odd) {
            sh[(t & 1) ^ 1][u] = hn;
            g_hs[t * HH + u]   = hn;
        }
        __syncthreads();
    }

    // ---- projection tail: out[t] = sigmoid(sum_u hs[t][u]*Wl[u] + b) ----
    const float bl = sbl;
    for (int t = tid; t < TT; t += 200) {
        const float4* hr = reinterpret_cast<const float4*>(g_hs + t * HH);
        float s0 = 0.0f, s1 = 0.0f;
        #pragma unroll
        for (int j = 0; j < 25; j++) {
            float4 hv = hr[j];
            const float* wl = sWl + 4 * j;
            s0 = fmaf(hv.x, wl[0], s0);
            s1 = fmaf(hv.y, wl[1], s1);
            s0 = fmaf(hv.z, wl[2], s0);
            s1 = fmaf(hv.w, wl[3], s1);
        }
        float z = s0 + s1 + bl;
        out[t] = rcp_approx(1.0f + ex2_approx(-LOG2E * z));
    }
}

// ---------------------------------------------------------------------------
// Launch.  Inputs: input_x, W_ih, W_hh, b_ih, b_hh, W_lin, b_lin
// ---------------------------------------------------------------------------
extern "C" void kernel_launch(void* const* d_in, const int* in_sizes, int n_in,
                              void* d_out, int out_size) {
    const float* x    = (const float*)d_in[0];
    const float* Wih  = (const float*)d_in[1];
    const float* Whh  = (const float*)d_in[2];
    const float* bih  = (const float*)d_in[3];
    const float* bhh  = (const float*)d_in[4];
    const float* Wlin = (const float*)d_in[5];
    const float* blin = (const float*)d_in[6];
    float* out = (float*)d_out;

    (void)in_sizes; (void)n_in; (void)out_size;

    const int smem_bytes = TT * 3 * (int)sizeof(float);   // 192 KB (x only)
    static bool attr_set = false;
    if (!attr_set) {
        cudaFuncSetAttribute(k_lstm_fused,
                             cudaFuncAttributeMaxDynamicSharedMemorySize,
                             smem_bytes);
        attr_set = true;
    }

    k_lstm_fused<<<1, 200, smem_bytes>>>(x, Whh, Wih, bih, bhh,
                                         Wlin, blin, out);
}